// round 5
// baseline (speedup 1.0000x reference)
#include <cuda_runtime.h>
#include <math.h>

#define CC 128
#define RB 32
#define NTHREADS 256

// shared float offsets
#define OFF_MM 0        // Xs (stage/phase1, 12288) aliased with mm (32x388 = 12416)
#define OFF_MS 12416    // ms[k][r] stride 36, k<256  (9216)
#define OFF_HS 21632    // hs[k][r] stride 36, k<128  (4608)
#define SMEM_FLOATS 26240
#define SMEM_BYTES (SMEM_FLOATS * 4)

// transposed weights in device scratch
__device__ float g_Ut[CC * CC];        // Ut[c][o] = U[o][c]
__device__ float g_Vt[CC * CC];
__device__ float g_W1t[2 * CC * CC];   // W1t[k][o]
__device__ float g_W2t[CC * 3 * CC];   // W2t[k][o]

typedef unsigned long long ull;

__device__ __forceinline__ void fma2(ull& d, ull a, ull b) {
    asm("fma.rn.f32x2 %0, %1, %2, %0;" : "+l"(d) : "l"(a), "l"(b));
}
__device__ __forceinline__ ull splat2(float x) {
    ull r; asm("mov.b64 %0, {%1, %1};" : "=l"(r) : "f"(x)); return r;
}
__device__ __forceinline__ float2 unpack2(ull v) {
    float2 f; asm("mov.b64 {%0, %1}, %2;" : "=f"(f.x), "=f"(f.y) : "l"(v)); return f;
}

// ---------------------------------------------------------------------------
__global__ void prep_kernel(const float* __restrict__ U, const float* __restrict__ V,
                            const float* __restrict__ W1, const float* __restrict__ W2) {
    int idx = blockIdx.x * blockDim.x + threadIdx.x;
    if (idx < 16384) {
        int c = idx >> 7, o = idx & 127;
        g_Ut[idx] = U[o * CC + c];
    } else if (idx < 32768) {
        int t = idx - 16384; int c = t >> 7, o = t & 127;
        g_Vt[t] = V[o * CC + c];
    } else if (idx < 65536) {
        int t = idx - 32768; int k = t >> 7, o = t & 127;
        g_W1t[t] = W1[o * 256 + k];
    } else if (idx < 114688) {
        int t = idx - 65536; int k = t / 384, o = t % 384;
        g_W2t[t] = W2[o * CC + k];
    }
}

// one K-pass of phase 1: acc[i][rp][c] (+=) X @ Wt, rows packed in f32x2 pairs
__device__ __forceinline__ void pass_uv(const float* __restrict__ Wt,
                                        const float* __restrict__ Xs,
                                        int r0, int c0, ull acc[3][2][4]) {
#pragma unroll
    for (int i = 0; i < 3; i++)
#pragma unroll
        for (int rp = 0; rp < 2; rp++)
#pragma unroll
            for (int c = 0; c < 4; c++) acc[i][rp][c] = 0ull;

#pragma unroll 2
    for (int k = 0; k < CC; k++) {
        float4 w = __ldg((const float4*)(Wt + k * CC + c0));
        ull ws[4] = {splat2(w.x), splat2(w.y), splat2(w.z), splat2(w.w)};
#pragma unroll
        for (int i = 0; i < 3; i++) {
            ulonglong2 xp = *(const ulonglong2*)(Xs + k * 96 + i * 32 + r0);
#pragma unroll
            for (int c = 0; c < 4; c++) {
                fma2(acc[i][0][c], xp.x, ws[c]);
                fma2(acc[i][1][c], xp.y, ws[c]);
            }
        }
    }
}

// ---------------------------------------------------------------------------
__global__ __launch_bounds__(NTHREADS, 2)
void fused_update_kernel(const float* __restrict__ vec,
                         const float* __restrict__ sca,
                         const float* __restrict__ b1g,
                         const float* __restrict__ b2g,
                         float* __restrict__ out,
                         int nrows) {
    extern __shared__ float sm[];
    float* Xs = sm + OFF_MM;   // phase1 input; aliased as mm in phase3+
    float* ms = sm + OFF_MS;   // [k<256][r], stride 36
    float* hs = sm + OFF_HS;   // [k<128][r], stride 36

    const int tid = threadIdx.x;
    const int tx = tid & 31, ty = tid >> 5;
    const int c0 = tx * 4;     // 4 output channels (phase 1/2 & epilogue)
    const int r0 = ty * 4;     // 4 rows
    const int row0 = blockIdx.x * RB;

    // ---- stage: vec -> Xs[c][i][r]; scalar -> ms[k][r]
    {
        const float4* vg = (const float4*)(vec + (size_t)row0 * 384);
        for (int idx = tid; idx < RB * 96; idx += NTHREADS) {
            int r = idx / 96, q = idx - r * 96;
            float4 f = vg[r * 96 + q];
            float vals[4] = {f.x, f.y, f.z, f.w};
            int e0 = q * 4;
#pragma unroll
            for (int j = 0; j < 4; j++) {
                int e = e0 + j; int c = e / 3, i = e - 3 * c;
                Xs[c * 96 + i * 32 + r] = vals[j];
            }
        }
        for (int idx = tid; idx < RB * CC; idx += NTHREADS) {
            int r = idx >> 7, k = idx & 127;
            ms[k * 36 + r] = sca[(size_t)(row0 + r) * CC + k];
        }
    }
    __syncthreads();

    // ---- Phase 1: two K-passes (U then V) to cap live registers
    ull aU[3][2][4];
    ull dotp[2][4];
    {
        pass_uv(g_Ut, Xs, r0, c0, aU);
        ull aV[3][2][4];
        pass_uv(g_Vt, Xs, r0, c0, aV);

        // dot = u.v (packed) ; vnorm -> ms[128+c][r] ; v dies here
#pragma unroll
        for (int rp = 0; rp < 2; rp++)
#pragma unroll
            for (int c = 0; c < 4; c++) {
                ull d = 0ull;
                fma2(d, aU[0][rp][c], aV[0][rp][c]);
                fma2(d, aU[1][rp][c], aV[1][rp][c]);
                fma2(d, aU[2][rp][c], aV[2][rp][c]);
                dotp[rp][c] = d;
                ull s = splat2(1e-8f);
                fma2(s, aV[0][rp][c], aV[0][rp][c]);
                fma2(s, aV[1][rp][c], aV[1][rp][c]);
                fma2(s, aV[2][rp][c], aV[2][rp][c]);
                float2 sv = unpack2(s);
                ms[(128 + c0 + c) * 36 + r0 + 2 * rp]     = sqrtf(sv.x);
                ms[(128 + c0 + c) * 36 + r0 + 2 * rp + 1] = sqrtf(sv.y);
            }
    }
    __syncthreads();

    // ---- Phase 2: h = silu(m @ W1t + b1), K=256, out [32 x 128]
    {
        ull acc[2][4];
#pragma unroll
        for (int rp = 0; rp < 2; rp++)
#pragma unroll
            for (int c = 0; c < 4; c++) acc[rp][c] = 0ull;

#pragma unroll 2
        for (int k = 0; k < 2 * CC; k++) {
            ulonglong2 xp = *(const ulonglong2*)(ms + k * 36 + r0);
            float4 w = __ldg((const float4*)(g_W1t + k * CC + c0));
            ull ws[4] = {splat2(w.x), splat2(w.y), splat2(w.z), splat2(w.w)};
#pragma unroll
            for (int c = 0; c < 4; c++) {
                fma2(acc[0][c], xp.x, ws[c]);
                fma2(acc[1][c], xp.y, ws[c]);
            }
        }
        float4 bias = __ldg((const float4*)(b1g + c0));
        float bb[4] = {bias.x, bias.y, bias.z, bias.w};
#pragma unroll
        for (int rp = 0; rp < 2; rp++)
#pragma unroll
            for (int c = 0; c < 4; c++) {
                float2 f = unpack2(acc[rp][c]);
                float x0 = f.x + bb[c], x1 = f.y + bb[c];
                hs[(c0 + c) * 36 + r0 + 2 * rp]     = x0 / (1.0f + __expf(-x0));
                hs[(c0 + c) * 36 + r0 + 2 * rp + 1] = x1 / (1.0f + __expf(-x1));
            }
    }
    __syncthreads();

    // ---- Phase 3: mm = h @ W2t + b2, K=128, out [32 x 384] (cols packed)
    {
        const int o0 = tx * 12;
        ull acc[4][6];
#pragma unroll
        for (int r = 0; r < 4; r++)
#pragma unroll
            for (int p = 0; p < 6; p++) acc[r][p] = 0ull;

#pragma unroll 2
        for (int k = 0; k < CC; k++) {
            float4 xv = *(const float4*)(hs + k * 36 + r0);
            ull xs[4] = {splat2(xv.x), splat2(xv.y), splat2(xv.z), splat2(xv.w)};
            const float* wrow = g_W2t + k * 384 + o0;
            ulonglong2 w0 = __ldg((const ulonglong2*)(wrow));
            ulonglong2 w1 = __ldg((const ulonglong2*)(wrow + 4));
            ulonglong2 w2 = __ldg((const ulonglong2*)(wrow + 8));
            ull wp[6] = {w0.x, w0.y, w1.x, w1.y, w2.x, w2.y};
#pragma unroll
            for (int r = 0; r < 4; r++)
#pragma unroll
                for (int p = 0; p < 6; p++) fma2(acc[r][p], xs[r], wp[p]);
        }
        float* mm = Xs;  // alias (Xs dead)
        float bb[12];
#pragma unroll
        for (int p = 0; p < 3; p++) {
            float4 f = __ldg((const float4*)(b2g + o0 + p * 4));
            bb[p * 4 + 0] = f.x; bb[p * 4 + 1] = f.y;
            bb[p * 4 + 2] = f.z; bb[p * 4 + 3] = f.w;
        }
#pragma unroll
        for (int r = 0; r < 4; r++)
#pragma unroll
            for (int p = 0; p < 6; p++) {
                float2 f = unpack2(acc[r][p]);
                float2 o = make_float2(f.x + bb[2 * p], f.y + bb[2 * p + 1]);
                *(float2*)(mm + (r0 + r) * 388 + o0 + 2 * p) = o;
            }
    }
    __syncthreads();

    // ---- Epilogue: delta_v = u*a ; delta_s = b + c*dot   (u, dot in regs)
    {
        const float* mm = Xs;
        float* out_ds = out + (size_t)nrows * 384;
#pragma unroll
        for (int r = 0; r < 4; r++) {
            const int rp = r >> 1, hl = r & 1;
            const int rr = r0 + r;
            float4 a4 = *(const float4*)(mm + rr * 388 + c0);
            float4 b4 = *(const float4*)(mm + rr * 388 + 128 + c0);
            float4 c4 = *(const float4*)(mm + rr * 388 + 256 + c0);
            float av[4] = {a4.x, a4.y, a4.z, a4.w};
            float bv[4] = {b4.x, b4.y, b4.z, b4.w};
            float cv[4] = {c4.x, c4.y, c4.z, c4.w};

            float o12[12], ds[4];
#pragma unroll
            for (int c = 0; c < 4; c++) {
                float2 d = unpack2(dotp[rp][c]);
                float dv = hl ? d.y : d.x;
                ds[c] = bv[c] + cv[c] * dv;
#pragma unroll
                for (int i = 0; i < 3; i++) {
                    float2 t = unpack2(aU[i][rp][c]);
                    float uval = hl ? t.y : t.x;
                    o12[c * 3 + i] = uval * av[c];
                }
            }
            float4* op = (float4*)(out + (size_t)(row0 + rr) * 384 + (size_t)c0 * 3);
            op[0] = make_float4(o12[0], o12[1], o12[2],  o12[3]);
            op[1] = make_float4(o12[4], o12[5], o12[6],  o12[7]);
            op[2] = make_float4(o12[8], o12[9], o12[10], o12[11]);
            *(float4*)(out_ds + (size_t)(row0 + rr) * CC + c0) =
                make_float4(ds[0], ds[1], ds[2], ds[3]);
        }
    }
}

// ---------------------------------------------------------------------------
extern "C" void kernel_launch(void* const* d_in, const int* in_sizes, int n_in,
                              void* d_out, int out_size) {
    const float* vec = (const float*)d_in[0];
    const float* sca = (const float*)d_in[1];
    const float* U   = (const float*)d_in[2];
    const float* V   = (const float*)d_in[3];
    const float* W1  = (const float*)d_in[4];
    const float* b1  = (const float*)d_in[5];
    const float* W2  = (const float*)d_in[6];
    const float* b2  = (const float*)d_in[7];
    float* out = (float*)d_out;

    int nrows = in_sizes[0] / (CC * 3);
    int nblocks = nrows / RB;

    prep_kernel<<<448, 256>>>(U, V, W1, W2);

    cudaFuncSetAttribute(fused_update_kernel,
                         cudaFuncAttributeMaxDynamicSharedMemorySize, SMEM_BYTES);
    fused_update_kernel<<<nblocks, NTHREADS, SMEM_BYTES>>>(vec, sca, b1, b2, out, nrows);
}

// round 6
// speedup vs baseline: 1.5064x; 1.5064x over previous
#include <cuda_runtime.h>
#include <math.h>

#define CC 128
#define RB 32
#define NTHREADS 256

// shared float offsets
#define OFF_MM 0        // Xs (stage/phase1, 12288) aliased with mm (32x388 = 12416)
#define OFF_MS 12416    // ms[k][r] stride 36, k<256  (9216)
#define OFF_HS 21632    // hs[k][r] stride 36, k<128  (4608)
#define SMEM_FLOATS 26240
#define SMEM_BYTES (SMEM_FLOATS * 4)

// transposed weights in device scratch
__device__ float g_Ut[CC * CC];        // Ut[c][o] = U[o][c]
__device__ float g_Vt[CC * CC];
__device__ float g_W1t[2 * CC * CC];   // W1t[k][o]
__device__ float g_W2t[CC * 3 * CC];   // W2t[k][o]

typedef unsigned long long ull;

__device__ __forceinline__ void fma2(ull& d, ull a, ull b) {
    asm("fma.rn.f32x2 %0, %1, %2, %0;" : "+l"(d) : "l"(a), "l"(b));
}
__device__ __forceinline__ ull splat2(float x) {
    ull r; asm("mov.b64 %0, {%1, %1};" : "=l"(r) : "f"(x)); return r;
}
__device__ __forceinline__ float2 unpack2(ull v) {
    float2 f; asm("mov.b64 {%0, %1}, %2;" : "=f"(f.x), "=f"(f.y) : "l"(v)); return f;
}

// ---------------------------------------------------------------------------
__global__ void prep_kernel(const float* __restrict__ U, const float* __restrict__ V,
                            const float* __restrict__ W1, const float* __restrict__ W2) {
    int idx = blockIdx.x * blockDim.x + threadIdx.x;
    if (idx < 16384) {
        int c = idx >> 7, o = idx & 127;
        g_Ut[idx] = U[o * CC + c];
    } else if (idx < 32768) {
        int t = idx - 16384; int c = t >> 7, o = t & 127;
        g_Vt[t] = V[o * CC + c];
    } else if (idx < 65536) {
        int t = idx - 32768; int k = t >> 7, o = t & 127;
        g_W1t[t] = W1[o * 256 + k];
    } else if (idx < 114688) {
        int t = idx - 65536; int k = t / 384, o = t % 384;
        g_W2t[t] = W2[o * CC + k];
    }
}

// one K-pass of phase 1: acc[i][rp][c] (+=) X @ Wt, rows packed in f32x2 pairs
__device__ __forceinline__ void pass_uv(const float* __restrict__ Wt,
                                        const float* __restrict__ Xs,
                                        int r0, int c0, ull acc[3][2][4]) {
#pragma unroll
    for (int i = 0; i < 3; i++)
#pragma unroll
        for (int rp = 0; rp < 2; rp++)
#pragma unroll
            for (int c = 0; c < 4; c++) acc[i][rp][c] = 0ull;

#pragma unroll 2
    for (int k = 0; k < CC; k++) {
        float4 w = __ldg((const float4*)(Wt + k * CC + c0));
        ull ws[4] = {splat2(w.x), splat2(w.y), splat2(w.z), splat2(w.w)};
#pragma unroll
        for (int i = 0; i < 3; i++) {
            ulonglong2 xp = *(const ulonglong2*)(Xs + k * 96 + i * 32 + r0);
#pragma unroll
            for (int c = 0; c < 4; c++) {
                fma2(acc[i][0][c], xp.x, ws[c]);
                fma2(acc[i][1][c], xp.y, ws[c]);
            }
        }
    }
}

// ---------------------------------------------------------------------------
__global__ __launch_bounds__(NTHREADS, 2)
void fused_update_kernel(const float* __restrict__ vec,
                         const float* __restrict__ sca,
                         const float* __restrict__ b1g,
                         const float* __restrict__ b2g,
                         float* __restrict__ out,
                         int nrows) {
    extern __shared__ float sm[];
    float* Xs = sm + OFF_MM;   // phase1 input; aliased as mm in phase3+
    float* ms = sm + OFF_MS;   // [k<256][r], stride 36
    float* hs = sm + OFF_HS;   // [k<128][r], stride 36

    const int tid = threadIdx.x;
    const int tx = tid & 31, ty = tid >> 5;
    const int c0 = tx * 4;     // 4 output channels (phase 1/2 & epilogue)
    const int r0 = ty * 4;     // 4 rows
    const int row0 = blockIdx.x * RB;

    // ---- stage: vec -> Xs[c][i][r]; scalar -> ms[k][r]
    {
        const float4* vg = (const float4*)(vec + (size_t)row0 * 384);
        for (int idx = tid; idx < RB * 96; idx += NTHREADS) {
            int r = idx / 96, q = idx - r * 96;
            float4 f = vg[r * 96 + q];
            float vals[4] = {f.x, f.y, f.z, f.w};
            int e0 = q * 4;
#pragma unroll
            for (int j = 0; j < 4; j++) {
                int e = e0 + j; int c = e / 3, i = e - 3 * c;
                Xs[c * 96 + i * 32 + r] = vals[j];
            }
        }
        for (int idx = tid; idx < RB * CC; idx += NTHREADS) {
            int r = idx >> 7, k = idx & 127;
            ms[k * 36 + r] = sca[(size_t)(row0 + r) * CC + k];
        }
    }
    __syncthreads();

    // ---- Phase 1: two K-passes (U then V) to cap live registers
    ull aU[3][2][4];
    ull dotp[2][4];
    {
        pass_uv(g_Ut, Xs, r0, c0, aU);
        ull aV[3][2][4];
        pass_uv(g_Vt, Xs, r0, c0, aV);

        // dot = u.v (packed) ; vnorm -> ms[128+c][r] ; v dies here
#pragma unroll
        for (int rp = 0; rp < 2; rp++)
#pragma unroll
            for (int c = 0; c < 4; c++) {
                ull d = 0ull;
                fma2(d, aU[0][rp][c], aV[0][rp][c]);
                fma2(d, aU[1][rp][c], aV[1][rp][c]);
                fma2(d, aU[2][rp][c], aV[2][rp][c]);
                dotp[rp][c] = d;
                ull s = splat2(1e-8f);
                fma2(s, aV[0][rp][c], aV[0][rp][c]);
                fma2(s, aV[1][rp][c], aV[1][rp][c]);
                fma2(s, aV[2][rp][c], aV[2][rp][c]);
                float2 sv = unpack2(s);
                ms[(128 + c0 + c) * 36 + r0 + 2 * rp]     = sqrtf(sv.x);
                ms[(128 + c0 + c) * 36 + r0 + 2 * rp + 1] = sqrtf(sv.y);
            }
    }
    __syncthreads();

    // ---- Phase 2: h = silu(m @ W1t + b1), K=256, out [32 x 128]
    {
        ull acc[2][4];
#pragma unroll
        for (int rp = 0; rp < 2; rp++)
#pragma unroll
            for (int c = 0; c < 4; c++) acc[rp][c] = 0ull;

#pragma unroll 2
        for (int k = 0; k < 2 * CC; k++) {
            ulonglong2 xp = *(const ulonglong2*)(ms + k * 36 + r0);
            float4 w = __ldg((const float4*)(g_W1t + k * CC + c0));
            ull ws[4] = {splat2(w.x), splat2(w.y), splat2(w.z), splat2(w.w)};
#pragma unroll
            for (int c = 0; c < 4; c++) {
                fma2(acc[0][c], xp.x, ws[c]);
                fma2(acc[1][c], xp.y, ws[c]);
            }
        }
        float4 bias = __ldg((const float4*)(b1g + c0));
        float bb[4] = {bias.x, bias.y, bias.z, bias.w};
#pragma unroll
        for (int rp = 0; rp < 2; rp++)
#pragma unroll
            for (int c = 0; c < 4; c++) {
                float2 f = unpack2(acc[rp][c]);
                float x0 = f.x + bb[c], x1 = f.y + bb[c];
                hs[(c0 + c) * 36 + r0 + 2 * rp]     = x0 / (1.0f + __expf(-x0));
                hs[(c0 + c) * 36 + r0 + 2 * rp + 1] = x1 / (1.0f + __expf(-x1));
            }
    }
    __syncthreads();

    // ---- Phase 3: mm = h @ W2t + b2, K=128, out [32 x 384] (cols packed)
    {
        const int o0 = tx * 12;
        ull acc[4][6];
#pragma unroll
        for (int r = 0; r < 4; r++)
#pragma unroll
            for (int p = 0; p < 6; p++) acc[r][p] = 0ull;

#pragma unroll 2
        for (int k = 0; k < CC; k++) {
            float4 xv = *(const float4*)(hs + k * 36 + r0);
            ull xs[4] = {splat2(xv.x), splat2(xv.y), splat2(xv.z), splat2(xv.w)};
            const float* wrow = g_W2t + k * 384 + o0;
            ulonglong2 w0 = __ldg((const ulonglong2*)(wrow));
            ulonglong2 w1 = __ldg((const ulonglong2*)(wrow + 4));
            ulonglong2 w2 = __ldg((const ulonglong2*)(wrow + 8));
            ull wp[6] = {w0.x, w0.y, w1.x, w1.y, w2.x, w2.y};
#pragma unroll
            for (int r = 0; r < 4; r++)
#pragma unroll
                for (int p = 0; p < 6; p++) fma2(acc[r][p], xs[r], wp[p]);
        }
        float* mm = Xs;  // alias (Xs dead)
        float bb[12];
#pragma unroll
        for (int p = 0; p < 3; p++) {
            float4 f = __ldg((const float4*)(b2g + o0 + p * 4));
            bb[p * 4 + 0] = f.x; bb[p * 4 + 1] = f.y;
            bb[p * 4 + 2] = f.z; bb[p * 4 + 3] = f.w;
        }
#pragma unroll
        for (int r = 0; r < 4; r++)
#pragma unroll
            for (int p = 0; p < 6; p++) {
                float2 f = unpack2(acc[r][p]);
                float2 o = make_float2(f.x + bb[2 * p], f.y + bb[2 * p + 1]);
                *(float2*)(mm + (r0 + r) * 388 + o0 + 2 * p) = o;
            }
    }
    __syncthreads();

    // ---- Epilogue: delta_v = u*a ; delta_s = b + c*dot   (u, dot in regs)
    {
        const float* mm = Xs;
        float* out_ds = out + (size_t)nrows * 384;
#pragma unroll
        for (int r = 0; r < 4; r++) {
            const int rp = r >> 1, hl = r & 1;
            const int rr = r0 + r;
            float4 a4 = *(const float4*)(mm + rr * 388 + c0);
            float4 b4 = *(const float4*)(mm + rr * 388 + 128 + c0);
            float4 c4 = *(const float4*)(mm + rr * 388 + 256 + c0);
            float av[4] = {a4.x, a4.y, a4.z, a4.w};
            float bv[4] = {b4.x, b4.y, b4.z, b4.w};
            float cv[4] = {c4.x, c4.y, c4.z, c4.w};

            float o12[12], ds[4];
#pragma unroll
            for (int c = 0; c < 4; c++) {
                float2 d = unpack2(dotp[rp][c]);
                float dv = hl ? d.y : d.x;
                ds[c] = bv[c] + cv[c] * dv;
#pragma unroll
                for (int i = 0; i < 3; i++) {
                    float2 t = unpack2(aU[i][rp][c]);
                    float uval = hl ? t.y : t.x;
                    o12[c * 3 + i] = uval * av[c];
                }
            }
            float4* op = (float4*)(out + (size_t)(row0 + rr) * 384 + (size_t)c0 * 3);
            op[0] = make_float4(o12[0], o12[1], o12[2],  o12[3]);
            op[1] = make_float4(o12[4], o12[5], o12[6],  o12[7]);
            op[2] = make_float4(o12[8], o12[9], o12[10], o12[11]);
            *(float4*)(out_ds + (size_t)(row0 + rr) * CC + c0) =
                make_float4(ds[0], ds[1], ds[2], ds[3]);
        }
    }
}

// ---------------------------------------------------------------------------
extern "C" void kernel_launch(void* const* d_in, const int* in_sizes, int n_in,
                              void* d_out, int out_size) {
    const float* vec = (const float*)d_in[0];
    const float* sca = (const float*)d_in[1];
    const float* U   = (const float*)d_in[2];
    const float* V   = (const float*)d_in[3];
    const float* W1  = (const float*)d_in[4];
    const float* b1  = (const float*)d_in[5];
    const float* W2  = (const float*)d_in[6];
    const float* b2  = (const float*)d_in[7];
    float* out = (float*)d_out;

    int nrows = in_sizes[0] / (CC * 3);
    int nblocks = nrows / RB;

    prep_kernel<<<448, 256>>>(U, V, W1, W2);

    cudaFuncSetAttribute(fused_update_kernel,
                         cudaFuncAttributeMaxDynamicSharedMemorySize, SMEM_BYTES);
    fused_update_kernel<<<nblocks, NTHREADS, SMEM_BYTES>>>(vec, sca, b1, b2, out, nrows);
}

// round 9
// speedup vs baseline: 3.0208x; 2.0054x over previous
#include <cuda_runtime.h>
#include <cuda_fp16.h>
#include <math.h>
#include <stdint.h>

#define NT 512
#define RB 64

// smem byte offsets
#define AH_OFF   0
#define AL_OFF   17408
#define W0H_OFF  34816
#define W0L_OFF  69632
#define W1H_OFF  104448
#define W1L_OFF  139264
#define DV_OFF   174080
#define SM_TOTAL 224256

// pre-split padded weights: 7 tiles of [128 n][136 k] halves
// tiles: 0=U, 1=V, 2=W1[:, :128], 3=W1[:, 128:], 4..6=W2 row-chunks
__device__ __align__(16) __half g_wh[7 * 128 * 136];
__device__ __align__(16) __half g_wl[7 * 128 * 136];

__device__ __forceinline__ uint32_t s2u(const void* p) {
    uint32_t a;
    asm("{ .reg .u64 t; cvta.to.shared.u64 t, %1; cvt.u32.u64 %0, t; }" : "=r"(a) : "l"(p));
    return a;
}

#define LDSM4(d, a) \
    asm volatile("ldmatrix.sync.aligned.m8n8.x4.shared.b16 {%0,%1,%2,%3}, [%4];" \
                 : "=r"((d)[0]), "=r"((d)[1]), "=r"((d)[2]), "=r"((d)[3]) : "r"(a))

__device__ __forceinline__ void mma_16816(float* d, const uint32_t a[4],
                                          uint32_t b0, uint32_t b1) {
    asm volatile(
        "mma.sync.aligned.m16n8k16.row.col.f32.f16.f16.f32 "
        "{%0,%1,%2,%3}, {%4,%5,%6,%7}, {%8,%9}, {%0,%1,%2,%3};"
        : "+f"(d[0]), "+f"(d[1]), "+f"(d[2]), "+f"(d[3])
        : "r"(a[0]), "r"(a[1]), "r"(a[2]), "r"(a[3]), "r"(b0), "r"(b1));
}

// K=128 GEMM: acc0 (+)= A x B0 [, acc1 (+)= A x B1], fp32-emulated in 3 fp16 passes
template <bool DUAL>
__device__ __forceinline__ void gemm_go(float* acc0, float* acc1,
                                        uint32_t aH0, uint32_t aH1,
                                        uint32_t aL0, uint32_t aL1,
                                        uint32_t b0H, uint32_t b0L,
                                        uint32_t b1H, uint32_t b1L) {
#pragma unroll
    for (int k0 = 0; k0 < 128; k0 += 16) {
        const uint32_t ko = (uint32_t)k0 * 2;
        uint32_t fah[2][4], fal[2][4], fbh[4], fbl[4];
        LDSM4(fah[0], aH0 + ko);
        LDSM4(fah[1], aH1 + ko);
        LDSM4(fal[0], aL0 + ko);
        LDSM4(fal[1], aL1 + ko);
        LDSM4(fbh, b0H + ko);
        LDSM4(fbl, b0L + ko);
#pragma unroll
        for (int mt = 0; mt < 2; mt++)
#pragma unroll
            for (int nt = 0; nt < 2; nt++) {
                float* d = acc0 + mt * 8 + nt * 4;
                mma_16816(d, fah[mt], fbh[nt * 2], fbh[nt * 2 + 1]);
                mma_16816(d, fah[mt], fbl[nt * 2], fbl[nt * 2 + 1]);
                mma_16816(d, fal[mt], fbh[nt * 2], fbh[nt * 2 + 1]);
            }
        if (DUAL) {
            uint32_t gbh[4], gbl[4];
            LDSM4(gbh, b1H + ko);
            LDSM4(gbl, b1L + ko);
#pragma unroll
            for (int mt = 0; mt < 2; mt++)
#pragma unroll
                for (int nt = 0; nt < 2; nt++) {
                    float* d = acc1 + mt * 8 + nt * 4;
                    mma_16816(d, fah[mt], gbh[nt * 2], gbh[nt * 2 + 1]);
                    mma_16816(d, fah[mt], gbl[nt * 2], gbl[nt * 2 + 1]);
                    mma_16816(d, fal[mt], gbh[nt * 2], gbh[nt * 2 + 1]);
                }
        }
    }
}

__device__ __forceinline__ void put_hl(__half* H, __half* L, int off, float x) {
    __half h = __float2half_rn(x);
    H[off] = h;
    L[off] = __float2half_rn(x - __half2float(h));
}

// ---------------------------------------------------------------------------
__global__ void prep_kernel(const float* __restrict__ U, const float* __restrict__ V,
                            const float* __restrict__ W1, const float* __restrict__ W2) {
    int idx = blockIdx.x * blockDim.x + threadIdx.x;
    if (idx >= 7 * 16384) return;
    int t = idx >> 14;
    int n = (idx >> 7) & 127;
    int k = idx & 127;
    float val;
    if (t == 0)      val = U[n * 128 + k];
    else if (t == 1) val = V[n * 128 + k];
    else if (t == 2) val = W1[n * 256 + k];
    else if (t == 3) val = W1[n * 256 + 128 + k];
    else             val = W2[((t - 4) * 128 + n) * 128 + k];
    __half h = __float2half_rn(val);
    __half l = __float2half_rn(val - __half2float(h));
    g_wh[t * 17408 + n * 136 + k] = h;
    g_wl[t * 17408 + n * 136 + k] = l;
}

// ---------------------------------------------------------------------------
__global__ __launch_bounds__(NT, 1)
void update_mma_kernel(const float* __restrict__ vec, const float* __restrict__ sca,
                       const float* __restrict__ b1g, const float* __restrict__ b2g,
                       float* __restrict__ out, int nrows) {
    extern __shared__ char sm[];
    const uint32_t smb = s2u(sm);
    __half* Ah = (__half*)(sm + AH_OFF);
    __half* Al = (__half*)(sm + AL_OFF);
    float*  DVf = (float*)(sm + DV_OFF);

    const int tid = threadIdx.x;
    const int lane = tid & 31;
    const int w = tid >> 5;
    const int wm = w & 1;    // M band (0/1): rows wm*32..+31
    const int wn = w >> 1;   // N band (0..7): cols wn*16..+15
    const int row0 = blockIdx.x * RB;

    // ldmatrix per-thread byte offsets (within a [.][136]-half region)
    const uint32_t aoff0 = ((wm * 32 + (lane & 7) + ((lane >> 3) & 1) * 8) * 136
                            + ((lane >> 4) & 1) * 8) * 2;
    const uint32_t aoff1 = aoff0 + 16 * 136 * 2;
    const uint32_t boff  = ((wn * 16 + ((lane >> 4) & 1) * 8 + (lane & 7)) * 136
                            + ((lane >> 3) & 1) * 8) * 2;

    const uint32_t AHb = smb + AH_OFF, ALb = smb + AL_OFF;
    const uint32_t W0H = smb + W0H_OFF, W0L = smb + W0L_OFF;
    const uint32_t W1H = smb + W1H_OFF, W1L = smb + W1L_OFF;

    // fragment ownership bases
    const int rbase = wm * 32 + (lane >> 2);
    const int cbase = wn * 16 + (lane & 3) * 2;

#define POS_LOOP(body) \
    _Pragma("unroll") for (int mt = 0; mt < 2; mt++) \
    _Pragma("unroll") for (int nt = 0; nt < 2; nt++) \
    _Pragma("unroll") for (int jj = 0; jj < 4; jj++) { \
        const int idx = mt * 8 + nt * 4 + jj; \
        const int row = rbase + mt * 16 + (jj >> 1) * 8; \
        const int col = cbase + nt * 8 + (jj & 1); \
        body \
    }

    // weight staging: tile t -> region (dstH, dstL)
    auto stage_w = [&](uint32_t dstH_off, uint32_t dstL_off, int t) {
        const uint4* shh = (const uint4*)(g_wh + t * 17408);
        const uint4* sll = (const uint4*)(g_wl + t * 17408);
        uint4* dh = (uint4*)(sm + dstH_off);
        uint4* dl = (uint4*)(sm + dstL_off);
        for (int i = tid; i < 2176; i += NT) { dh[i] = shh[i]; dl[i] = sll[i]; }
    };
    // A stage from vec component i
    auto stage_a_vec = [&](int i) {
        for (int e = tid; e < RB * 128; e += NT) {
            int r = e >> 7, c = e & 127;
            float x = __ldg(vec + (size_t)(row0 + r) * 384 + c * 3 + i);
            put_hl(Ah, Al, r * 136 + c, x);
        }
    };

    // ---- phase 1: u,v per component; fold dot/ssq ----
    stage_w(W0H_OFF, W0L_OFF, 0);   // U
    stage_w(W1H_OFF, W1L_OFF, 1);   // V
    float dotv[16], ssq[16];
#pragma unroll
    for (int j = 0; j < 16; j++) { dotv[j] = 0.0f; ssq[j] = 1e-8f; }

    for (int i = 0; i < 3; i++) {
        __syncthreads();
        stage_a_vec(i);
        __syncthreads();
        float uacc[16], vacc[16];
#pragma unroll
        for (int j = 0; j < 16; j++) { uacc[j] = 0.0f; vacc[j] = 0.0f; }
        gemm_go<true>(uacc, vacc, AHb + aoff0, AHb + aoff1, ALb + aoff0, ALb + aoff1,
                      W0H + boff, W0L + boff, W1H + boff, W1L + boff);
#pragma unroll
        for (int j = 0; j < 16; j++) {
            dotv[j] += uacc[j] * vacc[j];
            ssq[j]  += vacc[j] * vacc[j];
        }
    }
    __syncthreads();

    // ---- phase 2: h = silu([s|vnorm] @ W1^T + b1) ----
    stage_w(W0H_OFF, W0L_OFF, 2);   // W1 k-chunk 0
    stage_w(W1H_OFF, W1L_OFF, 3);   // W1 k-chunk 1
    for (int e = tid; e < RB * 128; e += NT) {  // A = scalar tile (coalesced)
        int r = e >> 7, c = e & 127;
        put_hl(Ah, Al, r * 136 + c, __ldg(sca + (size_t)(row0 + r) * 128 + c));
    }
    __syncthreads();
    float hacc[16];
#pragma unroll
    for (int j = 0; j < 16; j++) hacc[j] = 0.0f;
    gemm_go<false>(hacc, hacc, AHb + aoff0, AHb + aoff1, ALb + aoff0, ALb + aoff1,
                   W0H + boff, W0L + boff, 0, 0);
    __syncthreads();
    POS_LOOP( put_hl(Ah, Al, row * 136 + col, sqrtf(ssq[idx])); )   // A = vnorm
    __syncthreads();
    gemm_go<false>(hacc, hacc, AHb + aoff0, AHb + aoff1, ALb + aoff0, ALb + aoff1,
                   W1H + boff, W1L + boff, 0, 0);
    __syncthreads();
    // A = silu(h)
    POS_LOOP(
        float x = hacc[idx] + __ldg(b1g + col);
        put_hl(Ah, Al, row * 136 + col, x / (1.0f + __expf(-x)));
    )
    stage_w(W0H_OFF, W0L_OFF, 4);   // W2a
    stage_w(W1H_OFF, W1L_OFF, 5);   // W2b
    __syncthreads();

    // ---- phase 3: a, b chunks (shared A) ----
    float aacc[16], bacc[16];
#pragma unroll
    for (int j = 0; j < 16; j++) { aacc[j] = 0.0f; bacc[j] = 0.0f; }
    gemm_go<true>(aacc, bacc, AHb + aoff0, AHb + aoff1, ALb + aoff0, ALb + aoff1,
                  W0H + boff, W0L + boff, W1H + boff, W1L + boff);
    float av[16], bv[16];
    POS_LOOP(
        av[idx] = aacc[idx] + __ldg(b2g + col);
        bv[idx] = bacc[idx] + __ldg(b2g + 128 + col);
    )
    __syncthreads();
    stage_w(W0H_OFF, W0L_OFF, 6);   // W2c
    stage_w(W1H_OFF, W1L_OFF, 0);   // U again (for epilogue recompute)
    __syncthreads();
    float cacc[16];
#pragma unroll
    for (int j = 0; j < 16; j++) cacc[j] = 0.0f;
    gemm_go<false>(cacc, cacc, AHb + aoff0, AHb + aoff1, ALb + aoff0, ALb + aoff1,
                   W0H + boff, W0L + boff, 0, 0);
    // ds = b + c*dot -> stage [64][132] in DV region (8443 floats max < 12544)
    POS_LOOP(
        float cx = cacc[idx] + __ldg(b2g + 256 + col);
        DVf[row * 132 + col] = bv[idx] + cx * dotv[idx];
    )
    __syncthreads();
    {
        float* out_ds = out + (size_t)nrows * 384;
        for (int f = tid; f < RB * 32; f += NT) {
            int r = f >> 5, q = f & 31;
            ((float4*)(out_ds + (size_t)(row0 + r) * 128))[q] = ((float4*)(DVf + r * 132))[q];
        }
    }

    // ---- epilogue: recompute u_i; hold ua[3][16] in regs ----
    float ua[3][16];
    for (int i = 0; i < 3; i++) {
        __syncthreads();
        stage_a_vec(i);
        __syncthreads();
        float uacc[16];
#pragma unroll
        for (int j = 0; j < 16; j++) uacc[j] = 0.0f;
        gemm_go<false>(uacc, uacc, AHb + aoff0, AHb + aoff1, ALb + aoff0, ALb + aoff1,
                       W1H + boff, W1L + boff, 0, 0);
#pragma unroll
        for (int j = 0; j < 16; j++) ua[i][j] = uacc[j] * av[j];
    }
    // write delta_v in two 32-row batches: DV [32][388] (12416 floats <= 12544)
    for (int p = 0; p < 2; p++) {
        __syncthreads();
        if (wm == p) {
            POS_LOOP(
                const int lr = row - p * 32;   // 0..31 within batch
#pragma unroll
                for (int i = 0; i < 3; i++)
                    DVf[lr * 388 + col * 3 + i] = ua[i][idx];
            )
        }
        __syncthreads();
        for (int f = tid; f < 32 * 96; f += NT) {
            int r = f / 96, q = f - r * 96;
            ((float4*)(out + (size_t)(row0 + p * 32 + r) * 384))[q] =
                ((float4*)(DVf + r * 388))[q];
        }
    }
#undef POS_LOOP
}

// ---------------------------------------------------------------------------
extern "C" void kernel_launch(void* const* d_in, const int* in_sizes, int n_in,
                              void* d_out, int out_size) {
    const float* vec = (const float*)d_in[0];  // [N, C, 3]
    const float* sca = (const float*)d_in[1];  // [N, C]
    const float* U   = (const float*)d_in[2];  // [C, C]
    const float* V   = (const float*)d_in[3];  // [C, C]
    const float* W1  = (const float*)d_in[4];  // [C, 2C]
    const float* b1  = (const float*)d_in[5];  // [C]
    const float* W2  = (const float*)d_in[6];  // [3C, C]
    const float* b2  = (const float*)d_in[7];  // [3C]
    float* out = (float*)d_out;

    int nrows = in_sizes[0] / 384;
    int nblocks = nrows / RB;

    prep_kernel<<<448, 256>>>(U, V, W1, W2);

    cudaFuncSetAttribute(update_mma_kernel,
                         cudaFuncAttributeMaxDynamicSharedMemorySize, SM_TOTAL);
    update_mma_kernel<<<nblocks, NT, SM_TOTAL>>>(vec, sca, b1, b2, out, nrows);
}

// round 10
// speedup vs baseline: 3.4242x; 1.1335x over previous
#include <cuda_runtime.h>
#include <cuda_fp16.h>
#include <math.h>
#include <stdint.h>

#define NT 512
#define RB 64

// smem byte offsets
#define AH_OFF   0
#define AL_OFF   17408
#define W0H_OFF  34816
#define W0L_OFF  69632
#define W1H_OFF  104448
#define W1L_OFF  139264
#define U16_OFF  174080          // u as fp16 [3][64][128] = 49152 B
#define SM_TOTAL 223232

// pre-split padded weights: 7 tiles of [128 n][136 k] halves
// tiles: 0=U, 1=V, 2=W1[:, :128], 3=W1[:, 128:], 4..6=W2 row-chunks
__device__ __align__(16) __half g_wh[7 * 128 * 136];
__device__ __align__(16) __half g_wl[7 * 128 * 136];

__device__ __forceinline__ uint32_t s2u(const void* p) {
    uint32_t a;
    asm("{ .reg .u64 t; cvta.to.shared.u64 t, %1; cvt.u32.u64 %0, t; }" : "=r"(a) : "l"(p));
    return a;
}

#define LDSM4(d, a) \
    asm volatile("ldmatrix.sync.aligned.m8n8.x4.shared.b16 {%0,%1,%2,%3}, [%4];" \
                 : "=r"((d)[0]), "=r"((d)[1]), "=r"((d)[2]), "=r"((d)[3]) : "r"(a))

__device__ __forceinline__ void mma_16816(float* d, const uint32_t a[4],
                                          uint32_t b0, uint32_t b1) {
    asm volatile(
        "mma.sync.aligned.m16n8k16.row.col.f32.f16.f16.f32 "
        "{%0,%1,%2,%3}, {%4,%5,%6,%7}, {%8,%9}, {%0,%1,%2,%3};"
        : "+f"(d[0]), "+f"(d[1]), "+f"(d[2]), "+f"(d[3])
        : "r"(a[0]), "r"(a[1]), "r"(a[2]), "r"(a[3]), "r"(b0), "r"(b1));
}

// K=128 GEMM: acc0 (+)= A x B0 [, acc1 (+)= A x B1], fp32-emulated in 3 fp16 passes
template <bool DUAL>
__device__ __forceinline__ void gemm_go(float* acc0, float* acc1,
                                        uint32_t aH0, uint32_t aH1,
                                        uint32_t aL0, uint32_t aL1,
                                        uint32_t b0H, uint32_t b0L,
                                        uint32_t b1H, uint32_t b1L) {
#pragma unroll
    for (int k0 = 0; k0 < 128; k0 += 16) {
        const uint32_t ko = (uint32_t)k0 * 2;
        uint32_t fah[2][4], fal[2][4], fbh[4], fbl[4];
        LDSM4(fah[0], aH0 + ko);
        LDSM4(fah[1], aH1 + ko);
        LDSM4(fal[0], aL0 + ko);
        LDSM4(fal[1], aL1 + ko);
        LDSM4(fbh, b0H + ko);
        LDSM4(fbl, b0L + ko);
#pragma unroll
        for (int mt = 0; mt < 2; mt++)
#pragma unroll
            for (int nt = 0; nt < 2; nt++) {
                float* d = acc0 + mt * 8 + nt * 4;
                mma_16816(d, fah[mt], fbh[nt * 2], fbh[nt * 2 + 1]);
                mma_16816(d, fah[mt], fbl[nt * 2], fbl[nt * 2 + 1]);
                mma_16816(d, fal[mt], fbh[nt * 2], fbh[nt * 2 + 1]);
            }
        if (DUAL) {
            uint32_t gbh[4], gbl[4];
            LDSM4(gbh, b1H + ko);
            LDSM4(gbl, b1L + ko);
#pragma unroll
            for (int mt = 0; mt < 2; mt++)
#pragma unroll
                for (int nt = 0; nt < 2; nt++) {
                    float* d = acc1 + mt * 8 + nt * 4;
                    mma_16816(d, fah[mt], gbh[nt * 2], gbh[nt * 2 + 1]);
                    mma_16816(d, fah[mt], gbl[nt * 2], gbl[nt * 2 + 1]);
                    mma_16816(d, fal[mt], gbh[nt * 2], gbh[nt * 2 + 1]);
                }
        }
    }
}

__device__ __forceinline__ void put_hl(__half* H, __half* L, int off, float x) {
    __half h = __float2half_rn(x);
    H[off] = h;
    L[off] = __float2half_rn(x - __half2float(h));
}

// ---------------------------------------------------------------------------
__global__ void prep_kernel(const float* __restrict__ U, const float* __restrict__ V,
                            const float* __restrict__ W1, const float* __restrict__ W2) {
    int idx = blockIdx.x * blockDim.x + threadIdx.x;
    if (idx >= 7 * 16384) return;
    int t = idx >> 14;
    int n = (idx >> 7) & 127;
    int k = idx & 127;
    float val;
    if (t == 0)      val = U[n * 128 + k];
    else if (t == 1) val = V[n * 128 + k];
    else if (t == 2) val = W1[n * 256 + k];
    else if (t == 3) val = W1[n * 256 + 128 + k];
    else             val = W2[((t - 4) * 128 + n) * 128 + k];
    __half h = __float2half_rn(val);
    __half l = __float2half_rn(val - __half2float(h));
    g_wh[t * 17408 + n * 136 + k] = h;
    g_wl[t * 17408 + n * 136 + k] = l;
}

// ---------------------------------------------------------------------------
__global__ __launch_bounds__(NT, 1)
void update_mma_kernel(const float* __restrict__ vec, const float* __restrict__ sca,
                       const float* __restrict__ b1g, const float* __restrict__ b2g,
                       float* __restrict__ out, int nrows) {
    extern __shared__ char sm[];
    const uint32_t smb = s2u(sm);
    __half* Ah = (__half*)(sm + AH_OFF);
    __half* Al = (__half*)(sm + AL_OFF);
    __half* Uh = (__half*)(sm + U16_OFF);  // [3][64][128] fp16

    const int tid = threadIdx.x;
    const int lane = tid & 31;
    const int w = tid >> 5;
    const int wm = w & 1;    // M band (0/1): rows wm*32..+31
    const int wn = w >> 1;   // N band (0..7): cols wn*16..+15
    const int row0 = blockIdx.x * RB;

    // ldmatrix per-thread byte offsets (within a [.][136]-half region)
    const uint32_t aoff0 = ((wm * 32 + (lane & 7) + ((lane >> 3) & 1) * 8) * 136
                            + ((lane >> 4) & 1) * 8) * 2;
    const uint32_t aoff1 = aoff0 + 16 * 136 * 2;
    const uint32_t boff  = ((wn * 16 + ((lane >> 4) & 1) * 8 + (lane & 7)) * 136
                            + ((lane >> 3) & 1) * 8) * 2;

    const uint32_t AHb = smb + AH_OFF, ALb = smb + AL_OFF;
    const uint32_t W0H = smb + W0H_OFF, W0L = smb + W0L_OFF;
    const uint32_t W1H = smb + W1H_OFF, W1L = smb + W1L_OFF;

    // fragment ownership bases
    const int rbase = wm * 32 + (lane >> 2);
    const int cbase = wn * 16 + (lane & 3) * 2;

#define POS_LOOP(body) \
    _Pragma("unroll") for (int mt = 0; mt < 2; mt++) \
    _Pragma("unroll") for (int nt = 0; nt < 2; nt++) \
    _Pragma("unroll") for (int jj = 0; jj < 4; jj++) { \
        const int idx = mt * 8 + nt * 4 + jj; \
        const int row = rbase + mt * 16 + (jj >> 1) * 8; \
        const int col = cbase + nt * 8 + (jj & 1); \
        body \
    }

    auto stage_w = [&](uint32_t dstH_off, uint32_t dstL_off, int t) {
        const uint4* shh = (const uint4*)(g_wh + t * 17408);
        const uint4* sll = (const uint4*)(g_wl + t * 17408);
        uint4* dh = (uint4*)(sm + dstH_off);
        uint4* dl = (uint4*)(sm + dstL_off);
        for (int i = tid; i < 2176; i += NT) { dh[i] = shh[i]; dl[i] = sll[i]; }
    };
    auto stage_a_vec = [&](int i) {
        for (int e = tid; e < RB * 128; e += NT) {
            int r = e >> 7, c = e & 127;
            float x = __ldg(vec + (size_t)(row0 + r) * 384 + c * 3 + i);
            put_hl(Ah, Al, r * 136 + c, x);
        }
    };

    // ---- phase 1: u,v per component; fold dot/ssq; stash u as fp16 ----
    stage_w(W0H_OFF, W0L_OFF, 0);   // U
    stage_w(W1H_OFF, W1L_OFF, 1);   // V
    float dotv[16], ssq[16];
#pragma unroll
    for (int j = 0; j < 16; j++) { dotv[j] = 0.0f; ssq[j] = 1e-8f; }

    for (int i = 0; i < 3; i++) {
        __syncthreads();            // prev GEMM done reading A (and W on i=0)
        stage_a_vec(i);
        __syncthreads();
        float uacc[16], vacc[16];
#pragma unroll
        for (int j = 0; j < 16; j++) { uacc[j] = 0.0f; vacc[j] = 0.0f; }
        gemm_go<true>(uacc, vacc, AHb + aoff0, AHb + aoff1, ALb + aoff0, ALb + aoff1,
                      W0H + boff, W0L + boff, W1H + boff, W1L + boff);
#pragma unroll
        for (int j = 0; j < 16; j++) {
            dotv[j] += uacc[j] * vacc[j];
            ssq[j]  += vacc[j] * vacc[j];
        }
        POS_LOOP( Uh[(i << 13) + (row << 7) + col] = __float2half_rn(uacc[idx]); )
    }
    __syncthreads();

    // ---- phase 2: h = silu([s|vnorm] @ W1^T + b1) ----
    stage_w(W0H_OFF, W0L_OFF, 2);   // W1 k-chunk 0
    stage_w(W1H_OFF, W1L_OFF, 3);   // W1 k-chunk 1
    for (int e = tid; e < RB * 128; e += NT) {  // A = scalar tile (coalesced)
        int r = e >> 7, c = e & 127;
        put_hl(Ah, Al, r * 136 + c, __ldg(sca + (size_t)(row0 + r) * 128 + c));
    }
    __syncthreads();
    float hacc[16];
#pragma unroll
    for (int j = 0; j < 16; j++) hacc[j] = 0.0f;
    gemm_go<false>(hacc, hacc, AHb + aoff0, AHb + aoff1, ALb + aoff0, ALb + aoff1,
                   W0H + boff, W0L + boff, 0, 0);
    __syncthreads();
    POS_LOOP( put_hl(Ah, Al, row * 136 + col, sqrtf(ssq[idx])); )   // A = vnorm
    __syncthreads();
    gemm_go<false>(hacc, hacc, AHb + aoff0, AHb + aoff1, ALb + aoff0, ALb + aoff1,
                   W1H + boff, W1L + boff, 0, 0);
    __syncthreads();
    // A = silu(h)
    POS_LOOP(
        float x = hacc[idx] + __ldg(b1g + col);
        put_hl(Ah, Al, row * 136 + col, x / (1.0f + __expf(-x)));
    )
    stage_w(W0H_OFF, W0L_OFF, 4);   // W2a
    stage_w(W1H_OFF, W1L_OFF, 5);   // W2b
    __syncthreads();

    // ---- phase 3: a, b chunks (shared A) ----
    float aacc[16], bacc[16];
#pragma unroll
    for (int j = 0; j < 16; j++) { aacc[j] = 0.0f; bacc[j] = 0.0f; }
    gemm_go<true>(aacc, bacc, AHb + aoff0, AHb + aoff1, ALb + aoff0, ALb + aoff1,
                  W0H + boff, W0L + boff, W1H + boff, W1L + boff);
    float av[16], bv[16];
    POS_LOOP(
        av[idx] = aacc[idx] + __ldg(b2g + col);
        bv[idx] = bacc[idx] + __ldg(b2g + 128 + col);
    )
    __syncthreads();                // dual GEMM done reading W0
    stage_w(W0H_OFF, W0L_OFF, 6);   // W2c
    __syncthreads();
    float cacc[16];
#pragma unroll
    for (int j = 0; j < 16; j++) cacc[j] = 0.0f;
    gemm_go<false>(cacc, cacc, AHb + aoff0, AHb + aoff1, ALb + aoff0, ALb + aoff1,
                   W0H + boff, W0L + boff, 0, 0);

    // ---- epilogue: direct global writes from fragment owners ----
    // delta_s = b + c*dot  (float2, 8B-aligned: col even at jj&1==0)
    {
        float* out_ds = out + (size_t)nrows * 384;
#pragma unroll
        for (int mt = 0; mt < 2; mt++)
#pragma unroll
            for (int nt = 0; nt < 2; nt++)
#pragma unroll
                for (int j2 = 0; j2 < 2; j2++) {
                    const int i0 = mt * 8 + nt * 4 + j2 * 2;
                    const int row = rbase + mt * 16 + j2 * 8;
                    const int c = cbase + nt * 8;
                    float c0 = cacc[i0]     + __ldg(b2g + 256 + c);
                    float c1 = cacc[i0 + 1] + __ldg(b2g + 256 + c + 1);
                    float2 d = make_float2(bv[i0] + c0 * dotv[i0],
                                           bv[i0 + 1] + c1 * dotv[i0 + 1]);
                    *(float2*)(out_ds + (size_t)(row0 + row) * 128 + c) = d;
                }
    }
    // delta_v = u16 * a  (3x float2 per (row, col-pair), 8B-aligned)
#pragma unroll
    for (int mt = 0; mt < 2; mt++)
#pragma unroll
        for (int nt = 0; nt < 2; nt++)
#pragma unroll
            for (int j2 = 0; j2 < 2; j2++) {
                const int i0 = mt * 8 + nt * 4 + j2 * 2;
                const int row = rbase + mt * 16 + j2 * 8;
                const int c = cbase + nt * 8;
                float a0 = av[i0], a1 = av[i0 + 1];
                float u0c = __half2float(Uh[(0 << 13) + (row << 7) + c]);
                float u1c = __half2float(Uh[(1 << 13) + (row << 7) + c]);
                float u2c = __half2float(Uh[(2 << 13) + (row << 7) + c]);
                float u0d = __half2float(Uh[(0 << 13) + (row << 7) + c + 1]);
                float u1d = __half2float(Uh[(1 << 13) + (row << 7) + c + 1]);
                float u2d = __half2float(Uh[(2 << 13) + (row << 7) + c + 1]);
                float* op = out + (size_t)(row0 + row) * 384 + (size_t)c * 3;
                ((float2*)op)[0] = make_float2(u0c * a0, u1c * a0);
                ((float2*)op)[1] = make_float2(u2c * a0, u0d * a1);
                ((float2*)op)[2] = make_float2(u1d * a1, u2d * a1);
            }
#undef POS_LOOP
}

// ---------------------------------------------------------------------------
extern "C" void kernel_launch(void* const* d_in, const int* in_sizes, int n_in,
                              void* d_out, int out_size) {
    const float* vec = (const float*)d_in[0];  // [N, C, 3]
    const float* sca = (const float*)d_in[1];  // [N, C]
    const float* U   = (const float*)d_in[2];  // [C, C]
    const float* V   = (const float*)d_in[3];  // [C, C]
    const float* W1  = (const float*)d_in[4];  // [C, 2C]
    const float* b1  = (const float*)d_in[5];  // [C]
    const float* W2  = (const float*)d_in[6];  // [3C, C]
    const float* b2  = (const float*)d_in[7];  // [3C]
    float* out = (float*)d_out;

    int nrows = in_sizes[0] / 384;
    int nblocks = nrows / RB;

    prep_kernel<<<448, 256>>>(U, V, W1, W2);

    cudaFuncSetAttribute(update_mma_kernel,
                         cudaFuncAttributeMaxDynamicSharedMemorySize, SM_TOTAL);
    update_mma_kernel<<<nblocks, NT, SM_TOTAL>>>(vec, sca, b1, b2, out, nrows);
}